// round 1
// baseline (speedup 1.0000x reference)
#include <cuda_runtime.h>
#include <math_constants.h>

#define DD   128
#define HH   4
#define MAXN 50048
#define MAXE 1600256

// ---------------- device scratch (no allocations allowed) ----------------
__device__ __align__(128) float g_K[MAXN * DD];
__device__ __align__(128) float g_Q[MAXN * DD];
__device__ __align__(128) float g_V[MAXN * DD];
__device__ int g_deg[MAXN];
__device__ int g_off[MAXN + 1];
__device__ int g_pos[MAXN];
__device__ int g_esrc[MAXE];

// ---------------- projection: Y = X @ W^T + b  (X:[n,128], W:[128,128]) ----
// BM=128, BN=128(full), BK=16, 256 threads, 8x8 register tile per thread.
__global__ void proj_kernel(const float* __restrict__ X,
                            const float* __restrict__ W,
                            const float* __restrict__ b,
                            int which, int n) {
    __shared__ float As[16][128];  // As[k][m]
    __shared__ float Bs[16][128];  // Bs[k][c] = W[c][k]

    float* __restrict__ Y = (which == 0) ? g_K : (which == 1) ? g_Q : g_V;

    const int tid = threadIdx.x;
    const int m0  = blockIdx.x * 128;
    const int tr  = tid >> 4;   // 0..15 -> rows tr*8 .. tr*8+7
    const int tc  = tid & 15;   // 0..15 -> cols tc*8 .. tc*8+7

    float acc[8][8];
#pragma unroll
    for (int i = 0; i < 8; i++)
#pragma unroll
        for (int j = 0; j < 8; j++) acc[i][j] = 0.f;

    for (int kk = 0; kk < DD; kk += 16) {
        // load A tile (128 rows x 16 k), 512 float4 total, 2 per thread
#pragma unroll
        for (int i = 0; i < 2; i++) {
            int f   = tid + i * 256;     // 0..511
            int row = f >> 2;            // 0..127
            int kq  = (f & 3) * 4;       // 0,4,8,12
            int gr  = m0 + row;
            float4 v = (gr < n) ? *(const float4*)&X[(long)gr * DD + kk + kq]
                                : make_float4(0.f, 0.f, 0.f, 0.f);
            As[kq + 0][row] = v.x; As[kq + 1][row] = v.y;
            As[kq + 2][row] = v.z; As[kq + 3][row] = v.w;
        }
        // load B tile: Bs[k][c] = W[c][kk+k]
#pragma unroll
        for (int i = 0; i < 2; i++) {
            int f  = tid + i * 256;
            int c  = f >> 2;
            int kq = (f & 3) * 4;
            float4 v = *(const float4*)&W[(long)c * DD + kk + kq];
            Bs[kq + 0][c] = v.x; Bs[kq + 1][c] = v.y;
            Bs[kq + 2][c] = v.z; Bs[kq + 3][c] = v.w;
        }
        __syncthreads();

#pragma unroll
        for (int k = 0; k < 16; k++) {
            float ar[8], br[8];
            *(float4*)&ar[0] = *(const float4*)&As[k][tr * 8];
            *(float4*)&ar[4] = *(const float4*)&As[k][tr * 8 + 4];
            *(float4*)&br[0] = *(const float4*)&Bs[k][tc * 8];
            *(float4*)&br[4] = *(const float4*)&Bs[k][tc * 8 + 4];
#pragma unroll
            for (int i = 0; i < 8; i++)
#pragma unroll
                for (int j = 0; j < 8; j++)
                    acc[i][j] = fmaf(ar[i], br[j], acc[i][j]);
        }
        __syncthreads();
    }

    // epilogue: add bias, store
    float bb[8];
#pragma unroll
    for (int j = 0; j < 8; j++) bb[j] = b[tc * 8 + j];
#pragma unroll
    for (int i = 0; i < 8; i++) {
        int gr = m0 + tr * 8 + i;
        if (gr < n) {
            float o[8];
#pragma unroll
            for (int j = 0; j < 8; j++) o[j] = acc[i][j] + bb[j];
            *(float4*)&Y[(long)gr * DD + tc * 8]     = *(float4*)&o[0];
            *(float4*)&Y[(long)gr * DD + tc * 8 + 4] = *(float4*)&o[4];
        }
    }
}

// ---------------- CSR build -----------------------------------------------
__global__ void zero_deg_kernel(int n) {
    int i = blockIdx.x * blockDim.x + threadIdx.x;
    if (i < n) g_deg[i] = 0;
}

__global__ void hist_kernel(const int* __restrict__ dst, int E) {
    int e = blockIdx.x * blockDim.x + threadIdx.x;
    if (e < E) atomicAdd(&g_deg[dst[e]], 1);
}

// single-block exclusive scan over n counters (n ~ 50k -> trivial cost)
__global__ void scan_kernel(int n) {
    __shared__ int sums[1024];
    int tid   = threadIdx.x;
    int chunk = (n + 1023) >> 10;
    int start = tid * chunk;
    int endi  = min(start + chunk, n);
    int s = 0;
    for (int i = start; i < endi; i++) s += g_deg[i];
    sums[tid] = s;
    __syncthreads();
    if (tid == 0) {
        int run = 0;
        for (int i = 0; i < 1024; i++) { int t = sums[i]; sums[i] = run; run += t; }
    }
    __syncthreads();
    int run = sums[tid];
    for (int i = start; i < endi; i++) {
        g_off[i] = run;
        g_pos[i] = run;
        run += g_deg[i];
    }
    if (endi == n) g_off[n] = run;  // total E (idempotent across threads)
}

__global__ void fill_kernel(const int* __restrict__ src,
                            const int* __restrict__ dst, int E) {
    int e = blockIdx.x * blockDim.x + threadIdx.x;
    if (e < E) {
        int p = atomicAdd(&g_pos[dst[e]], 1);
        g_esrc[p] = src[e];
    }
}

// ---------------- fused edge-softmax + aggregate ---------------------------
// One warp per destination node. Online softmax over incoming edges.
// Lane l owns output elements [4l, 4l+4); head h = l>>3 (dk = dv = 32).
__global__ void aggregate_kernel(float* __restrict__ out, int n) {
    int gw   = (blockIdx.x * blockDim.x + threadIdx.x) >> 5;
    int lane = threadIdx.x & 31;
    if (gw >= n) return;
    const int node = gw;

    const int beg = g_off[node];
    const int end = g_off[node + 1];

    const float4 q4 = *(const float4*)&g_Q[(long)node * DD + lane * 4];

    float  m = -CUDART_INF_F;
    float  d = 0.f;
    float4 acc = make_float4(0.f, 0.f, 0.f, 0.f);

    for (int e0 = beg; e0 < end; e0 += 32) {
        int mysrc = (e0 + lane < end) ? g_esrc[e0 + lane] : 0;
        int cnt   = min(32, end - e0);
        for (int j = 0; j < cnt; j++) {
            int sj = __shfl_sync(0xffffffffu, mysrc, j);

            const float4 k4 = *(const float4*)&g_K[(long)sj * DD + lane * 4];
            float sc = k4.x * q4.x + k4.y * q4.y + k4.z * q4.z + k4.w * q4.w;
            // reduce within the 8-lane head group (lanes share bits >= 3)
            sc += __shfl_xor_sync(0xffffffffu, sc, 1);
            sc += __shfl_xor_sync(0xffffffffu, sc, 2);
            sc += __shfl_xor_sync(0xffffffffu, sc, 4);

            float nm    = fmaxf(m, sc);
            float scale = __expf(m - nm);   // m=-inf -> 0
            float p     = __expf(sc - nm);
            d = d * scale + p;

            const float4 v4 = *(const float4*)&g_V[(long)sj * DD + lane * 4];
            acc.x = acc.x * scale + p * v4.x;
            acc.y = acc.y * scale + p * v4.y;
            acc.z = acc.z * scale + p * v4.z;
            acc.w = acc.w * scale + p * v4.w;
            m = nm;
        }
    }

    float inv = (d > 0.f) ? (1.f / d) : 0.f;
    float4 o = make_float4(acc.x * inv, acc.y * inv, acc.z * inv, acc.w * inv);
    *(float4*)&out[(long)node * DD + lane * 4] = o;
}

// ---------------- launch ----------------------------------------------------
extern "C" void kernel_launch(void* const* d_in, const int* in_sizes, int n_in,
                              void* d_out, int out_size) {
    const float* x  = (const float*)d_in[0];
    const float* Wk = (const float*)d_in[1];
    const float* bk = (const float*)d_in[2];
    const float* Wq = (const float*)d_in[3];
    const float* bq = (const float*)d_in[4];
    const float* Wv = (const float*)d_in[5];
    const float* bv = (const float*)d_in[6];
    const int*  src = (const int*)d_in[7];
    const int*  dst = (const int*)d_in[8];
    float* out = (float*)d_out;

    const int n = in_sizes[0] / DD;   // 50000
    const int E = in_sizes[7];        // 1600000

    // projections
    int gb = (n + 127) / 128;
    proj_kernel<<<gb, 256>>>(x, Wk, bk, 0, n);
    proj_kernel<<<gb, 256>>>(x, Wq, bq, 1, n);
    proj_kernel<<<gb, 256>>>(x, Wv, bv, 2, n);

    // CSR by destination
    zero_deg_kernel<<<(n + 255) / 256, 256>>>(n);
    hist_kernel<<<(E + 255) / 256, 256>>>(dst, E);
    scan_kernel<<<1, 1024>>>(n);
    fill_kernel<<<(E + 255) / 256, 256>>>(src, dst, E);

    // fused softmax + aggregate (1 warp / node)
    int totalThreads = n * 32;
    aggregate_kernel<<<(totalThreads + 255) / 256, 256>>>(out, n);
}